// round 1
// baseline (speedup 1.0000x reference)
#include <cuda_runtime.h>

// Fused gauss-attention for N=262144, T=1, S=9, E=32, H=2, HD=16.
// Strategy: fold in_proj/out_proj weights into per-head merged 32x32 matrices
// (prologue kernel), then one thread per batch element streams its
// query/key/value/gauss rows and writes 32 output floats. Memory-bound.

#define SEQ 9

// Merged weights (computed by prep_kernel each launch; deterministic).
__device__ float g_P[2 * 32 * 32];   // P_h[g][e] = 0.25 * sum_d wk[h16+d][g]*wq[h16+d][e]
__device__ float g_M[2 * 32 * 32];   // M_h[f][g] = sum_d opw[f][h16+d]*wv[h16+d][g]
__device__ float g_rb[2 * 32];       // 0.25 * sum_d bq[h16+d]*wk[h16+d][g]
__device__ float g_u[2 * 32];        // 0.25 * sum_d wq[h16+d][e]*bk[h16+d]
__device__ float g_t0[2];            // 0.25 * sum_d bq*bk
__device__ float g_D[32];            // opb[f] + sum_e opw[f][e]*bv[e]

__global__ void prep_kernel(const float* __restrict__ ipw,
                            const float* __restrict__ ipb,
                            const float* __restrict__ opw,
                            const float* __restrict__ opb) {
    const float* wq = ipw;            // [32][32] row f = out feature, col = in feature
    const float* wk = ipw + 1024;
    const float* wv = ipw + 2048;
    const float* bq = ipb;
    const float* bk = ipb + 32;
    const float* bv = ipb + 64;
    int tid = threadIdx.x;

    for (int idx = tid; idx < 2048; idx += blockDim.x) {
        int h = idx >> 10;
        int a = (idx >> 5) & 31;   // P: g ; M: output row f
        int c = idx & 31;          // P: e ; M: input col g
        float accP = 0.f, accM = 0.f;
        #pragma unroll
        for (int d = 0; d < 16; d++) {
            int f = h * 16 + d;
            accP += wk[f * 32 + a] * wq[f * 32 + c];
            accM += opw[a * 32 + f] * wv[f * 32 + c];
        }
        g_P[idx] = 0.25f * accP;
        g_M[idx] = accM;
    }
    if (tid < 64) {
        int h = tid >> 5, j = tid & 31;
        float arb = 0.f, au = 0.f;
        #pragma unroll
        for (int d = 0; d < 16; d++) {
            int f = h * 16 + d;
            arb += bq[f] * wk[f * 32 + j];
            au  += wq[f * 32 + j] * bk[f];
        }
        g_rb[tid] = 0.25f * arb;
        g_u[tid]  = 0.25f * au;
    }
    if (tid < 32) {
        float acc = opb[tid];
        #pragma unroll
        for (int e = 0; e < 32; e++) acc += opw[tid * 32 + e] * bv[e];
        g_D[tid] = acc;
    }
    if (tid < 2) {
        float acc = 0.f;
        #pragma unroll
        for (int d = 0; d < 16; d++) acc += bq[tid * 16 + d] * bk[tid * 16 + d];
        g_t0[tid] = 0.25f * acc;
    }
}

__global__ void __launch_bounds__(256)
attn_kernel(const float* __restrict__ query, const float* __restrict__ key,
            const float* __restrict__ value, const float* __restrict__ gauss,
            float* __restrict__ out, int n) {
    __shared__ float sP[2048];
    __shared__ float sM[2048];
    __shared__ float srb[64];
    __shared__ float su[64];
    __shared__ float st0[2];
    __shared__ float sD[32];

    for (int i = threadIdx.x; i < 2048; i += 256) {
        sP[i] = g_P[i];
        sM[i] = g_M[i];
    }
    if (threadIdx.x < 64) { srb[threadIdx.x] = g_rb[threadIdx.x]; su[threadIdx.x] = g_u[threadIdx.x]; }
    if (threadIdx.x < 32) sD[threadIdx.x] = g_D[threadIdx.x];
    if (threadIdx.x < 2)  st0[threadIdx.x] = g_t0[threadIdx.x];
    __syncthreads();

    int b = blockIdx.x * 256 + threadIdx.x;
    if (b >= n) return;

    // ---- load Q row (32 floats) ----
    float q[32];
    const float4* q4 = (const float4*)(query + (size_t)b * 32);
    #pragma unroll
    for (int j = 0; j < 8; j++) {
        float4 t = q4[j];
        q[4 * j + 0] = t.x; q[4 * j + 1] = t.y; q[4 * j + 2] = t.z; q[4 * j + 3] = t.w;
    }

    // ---- r_h = P_h q + rb_h  (pre-scaled by 0.25) ----
    float r0[32], r1[32];
    const float4* P0 = (const float4*)sP;
    const float4* P1 = (const float4*)(sP + 1024);
    #pragma unroll
    for (int g = 0; g < 32; g++) {
        float a0 = srb[g], a1 = srb[32 + g];
        #pragma unroll
        for (int e4 = 0; e4 < 8; e4++) {
            float4 p0 = P0[g * 8 + e4];
            float4 p1 = P1[g * 8 + e4];
            a0 = fmaf(p0.x, q[4 * e4 + 0], a0);
            a0 = fmaf(p0.y, q[4 * e4 + 1], a0);
            a0 = fmaf(p0.z, q[4 * e4 + 2], a0);
            a0 = fmaf(p0.w, q[4 * e4 + 3], a0);
            a1 = fmaf(p1.x, q[4 * e4 + 0], a1);
            a1 = fmaf(p1.y, q[4 * e4 + 1], a1);
            a1 = fmaf(p1.z, q[4 * e4 + 2], a1);
            a1 = fmaf(p1.w, q[4 * e4 + 3], a1);
        }
        r0[g] = a0; r1[g] = a1;
    }
    float t0 = st0[0], t1 = st0[1];
    #pragma unroll
    for (int e = 0; e < 32; e++) {
        t0 = fmaf(su[e], q[e], t0);
        t1 = fmaf(su[32 + e], q[e], t1);
    }

    // ---- logits over S=9 keys (scaled dot * gauss weight) ----
    const float4* k4 = (const float4*)(key + (size_t)b * 288);
    const float* gp = gauss + (size_t)b * SEQ;
    float l0[SEQ], l1[SEQ];
    #pragma unroll
    for (int s = 0; s < SEQ; s++) {
        float d0 = t0, d1 = t1;
        #pragma unroll
        for (int e4 = 0; e4 < 8; e4++) {
            float4 kv = k4[s * 8 + e4];
            d0 = fmaf(r0[4 * e4 + 0], kv.x, d0);
            d0 = fmaf(r0[4 * e4 + 1], kv.y, d0);
            d0 = fmaf(r0[4 * e4 + 2], kv.z, d0);
            d0 = fmaf(r0[4 * e4 + 3], kv.w, d0);
            d1 = fmaf(r1[4 * e4 + 0], kv.x, d1);
            d1 = fmaf(r1[4 * e4 + 1], kv.y, d1);
            d1 = fmaf(r1[4 * e4 + 2], kv.z, d1);
            d1 = fmaf(r1[4 * e4 + 3], kv.w, d1);
        }
        float gw = __expf(-10.0f * gp[s]);   // SIGMA = 10
        l0[s] = d0 * gw;
        l1[s] = d1 * gw;
    }

    // ---- softmax over S per head ----
    float m0 = l0[0], m1 = l1[0];
    #pragma unroll
    for (int s = 1; s < SEQ; s++) { m0 = fmaxf(m0, l0[s]); m1 = fmaxf(m1, l1[s]); }
    float p0[SEQ], p1[SEQ];
    float sum0 = 0.f, sum1 = 0.f;
    #pragma unroll
    for (int s = 0; s < SEQ; s++) {
        p0[s] = __expf(l0[s] - m0); sum0 += p0[s];
        p1[s] = __expf(l1[s] - m1); sum1 += p1[s];
    }
    float inv0 = __frcp_rn(sum0), inv1 = __frcp_rn(sum1);
    #pragma unroll
    for (int s = 0; s < SEQ; s++) { p0[s] *= inv0; p1[s] *= inv1; }

    // ---- weighted value sums (per head, over raw V rows) ----
    float vs0[32], vs1[32];
    #pragma unroll
    for (int g = 0; g < 32; g++) { vs0[g] = 0.f; vs1[g] = 0.f; }
    const float4* v4 = (const float4*)(value + (size_t)b * 288);
    #pragma unroll
    for (int s = 0; s < SEQ; s++) {
        float w0 = p0[s], w1 = p1[s];
        #pragma unroll
        for (int e4 = 0; e4 < 8; e4++) {
            float4 vv = v4[s * 8 + e4];
            vs0[4 * e4 + 0] = fmaf(w0, vv.x, vs0[4 * e4 + 0]);
            vs0[4 * e4 + 1] = fmaf(w0, vv.y, vs0[4 * e4 + 1]);
            vs0[4 * e4 + 2] = fmaf(w0, vv.z, vs0[4 * e4 + 2]);
            vs0[4 * e4 + 3] = fmaf(w0, vv.w, vs0[4 * e4 + 3]);
            vs1[4 * e4 + 0] = fmaf(w1, vv.x, vs1[4 * e4 + 0]);
            vs1[4 * e4 + 1] = fmaf(w1, vv.y, vs1[4 * e4 + 1]);
            vs1[4 * e4 + 2] = fmaf(w1, vv.z, vs1[4 * e4 + 2]);
            vs1[4 * e4 + 3] = fmaf(w1, vv.w, vs1[4 * e4 + 3]);
        }
    }

    // ---- out[f] = M0[f]·vs0 + M1[f]·vs1 + D[f] ----
    const float4* M0 = (const float4*)sM;
    const float4* M1 = (const float4*)(sM + 1024);
    float4* o4 = (float4*)(out + (size_t)b * 32);
    #pragma unroll
    for (int f4 = 0; f4 < 8; f4++) {
        float ov[4];
        #pragma unroll
        for (int kk = 0; kk < 4; kk++) {
            int f = f4 * 4 + kk;
            float acc = sD[f];
            #pragma unroll
            for (int g4 = 0; g4 < 8; g4++) {
                float4 m0v = M0[f * 8 + g4];
                float4 m1v = M1[f * 8 + g4];
                acc = fmaf(m0v.x, vs0[4 * g4 + 0], acc);
                acc = fmaf(m0v.y, vs0[4 * g4 + 1], acc);
                acc = fmaf(m0v.z, vs0[4 * g4 + 2], acc);
                acc = fmaf(m0v.w, vs0[4 * g4 + 3], acc);
                acc = fmaf(m1v.x, vs1[4 * g4 + 0], acc);
                acc = fmaf(m1v.y, vs1[4 * g4 + 1], acc);
                acc = fmaf(m1v.z, vs1[4 * g4 + 2], acc);
                acc = fmaf(m1v.w, vs1[4 * g4 + 3], acc);
            }
            ov[kk] = acc;
        }
        o4[f4] = make_float4(ov[0], ov[1], ov[2], ov[3]);
    }
}

extern "C" void kernel_launch(void* const* d_in, const int* in_sizes, int n_in,
                              void* d_out, int out_size) {
    const float* query = (const float*)d_in[0];
    const float* key   = (const float*)d_in[1];
    const float* value = (const float*)d_in[2];
    const float* gauss = (const float*)d_in[3];
    const float* ipw   = (const float*)d_in[4];
    const float* ipb   = (const float*)d_in[5];
    const float* opw   = (const float*)d_in[6];
    const float* opb   = (const float*)d_in[7];
    float* out = (float*)d_out;

    int n = in_sizes[0] / 32;   // N batch elements (T=1, E=32)

    prep_kernel<<<1, 256>>>(ipw, ipb, opw, opb);
    attn_kernel<<<(n + 255) / 256, 256>>>(query, key, value, gauss, out, n);
}

// round 3
// speedup vs baseline: 1.2068x; 1.2068x over previous
#include <cuda_runtime.h>

// Fused gauss-attention, N=262144, T=1, S=9, E=32, H=2, HD=16.
// Round 3: Round-2 coalesced staging design + 16B alignment fix on all
// shared arrays accessed via float4 (misaligned-address root cause).

#define SEQ 9

// Merged weights (computed by prep_kernel each launch; deterministic).
__device__ float g_P[2 * 32 * 32];   // P_h[g][e] = 0.25 * sum_d wk[h16+d][g]*wq[h16+d][e]
__device__ float g_M[2 * 32 * 32];   // M_h[f][g] = sum_d opw[f][h16+d]*wv[h16+d][g]
__device__ float g_rb[2 * 32];
__device__ float g_u[2 * 32];
__device__ float g_t0[2];
__device__ float g_D[32];

__global__ void prep_kernel(const float* __restrict__ ipw,
                            const float* __restrict__ ipb,
                            const float* __restrict__ opw,
                            const float* __restrict__ opb) {
    const float* wq = ipw;
    const float* wk = ipw + 1024;
    const float* wv = ipw + 2048;
    const float* bq = ipb;
    const float* bk = ipb + 32;
    const float* bv = ipb + 64;
    int tid = threadIdx.x;

    for (int idx = tid; idx < 2048; idx += blockDim.x) {
        int h = idx >> 10;
        int a = (idx >> 5) & 31;
        int c = idx & 31;
        float accP = 0.f, accM = 0.f;
        #pragma unroll
        for (int d = 0; d < 16; d++) {
            int f = h * 16 + d;
            accP += wk[f * 32 + a] * wq[f * 32 + c];
            accM += opw[a * 32 + f] * wv[f * 32 + c];
        }
        g_P[idx] = 0.25f * accP;
        g_M[idx] = accM;
    }
    if (tid < 64) {
        int h = tid >> 5, j = tid & 31;
        float arb = 0.f, au = 0.f;
        #pragma unroll
        for (int d = 0; d < 16; d++) {
            int f = h * 16 + d;
            arb += bq[f] * wk[f * 32 + j];
            au  += wq[f * 32 + j] * bk[f];
        }
        g_rb[tid] = 0.25f * arb;
        g_u[tid]  = 0.25f * au;
    }
    if (tid < 32) {
        float acc = opb[tid];
        #pragma unroll
        for (int e = 0; e < 32; e++) acc += opw[tid * 32 + e] * bv[e];
        g_D[tid] = acc;
    }
    if (tid < 2) {
        float acc = 0.f;
        #pragma unroll
        for (int d = 0; d < 16; d++) acc += bq[tid * 16 + d] * bk[tid * 16 + d];
        g_t0[tid] = 0.25f * acc;
    }
}

// Per-warp staging tile: 32 rows x 36 floats (pad 4 -> conflict-free STS.128/LDS.128;
// 36 floats = 144B per row keeps 16B alignment of every row base).
#define ROWSTRIDE 36

__global__ void __launch_bounds__(128)
attn_kernel(const float* __restrict__ query, const float* __restrict__ key,
            const float* __restrict__ value, const float* __restrict__ gauss,
            float* __restrict__ out, int n) {
    __shared__ __align__(16) float sP[2048];
    __shared__ __align__(16) float sM[2048];
    __shared__ __align__(16) float stagebuf[4][32 * ROWSTRIDE];   // 4 warps
    __shared__ float srb[64];
    __shared__ float su[64];
    __shared__ float st0[2];
    __shared__ float sD[32];
    __shared__ float gbuf[4][288];

    int tid = threadIdx.x;
    for (int i = tid; i < 2048; i += 128) {
        sP[i] = g_P[i];
        sM[i] = g_M[i];
    }
    if (tid < 64) { srb[tid] = g_rb[tid]; su[tid] = g_u[tid]; }
    if (tid < 32) sD[tid] = g_D[tid];
    if (tid < 2)  st0[tid] = g_t0[tid];
    __syncthreads();

    const int warp = tid >> 5;
    const int lane = tid & 31;
    const int B0 = blockIdx.x * 128 + warp * 32;
    if (B0 >= n) return;                 // whole-warp uniform
    float* buf = stagebuf[warp];
    float* gb  = gbuf[warp];

    const int maxrow = n - 1 - B0;       // clamp for (impossible here) partial warps

    // ---- stage gauss: 288 contiguous floats ----
    {
        const float* gsrc = gauss + (size_t)B0 * SEQ;
        int lim = (n - B0) * SEQ;
        #pragma unroll
        for (int i = 0; i < 9; i++) {
            int j = lane + 32 * i;
            gb[j] = gsrc[j < lim ? j : 0];
        }
    }

    // ---- stage Q (32 rows x 32 floats, contiguous slab) ----
    {
        const float4* qsrc = (const float4*)(query + (size_t)B0 * 32);
        #pragma unroll
        for (int p = 0; p < 8; p++) {
            int f = p * 32 + lane;
            int row = f >> 3, c4 = f & 7;
            int r = row <= maxrow ? row : maxrow;
            float4 v = qsrc[r * 8 + c4];
            *(float4*)&buf[row * ROWSTRIDE + c4 * 4] = v;
        }
    }
    __syncwarp();

    float q[32];
    #pragma unroll
    for (int e4 = 0; e4 < 8; e4++) {
        float4 v = *(const float4*)&buf[lane * ROWSTRIDE + e4 * 4];
        q[4 * e4 + 0] = v.x; q[4 * e4 + 1] = v.y; q[4 * e4 + 2] = v.z; q[4 * e4 + 3] = v.w;
    }

    // ---- r_h = P_h q + rb_h (pre-scaled by 0.25); uniform smem reads ----
    float r0[32], r1[32];
    const float4* P0 = (const float4*)sP;
    const float4* P1 = (const float4*)(sP + 1024);
    #pragma unroll
    for (int g = 0; g < 32; g++) {
        float a0 = srb[g], a1 = srb[32 + g];
        #pragma unroll
        for (int e4 = 0; e4 < 8; e4++) {
            float4 p0 = P0[g * 8 + e4];
            float4 p1 = P1[g * 8 + e4];
            a0 = fmaf(p0.x, q[4 * e4 + 0], a0);
            a0 = fmaf(p0.y, q[4 * e4 + 1], a0);
            a0 = fmaf(p0.z, q[4 * e4 + 2], a0);
            a0 = fmaf(p0.w, q[4 * e4 + 3], a0);
            a1 = fmaf(p1.x, q[4 * e4 + 0], a1);
            a1 = fmaf(p1.y, q[4 * e4 + 1], a1);
            a1 = fmaf(p1.z, q[4 * e4 + 2], a1);
            a1 = fmaf(p1.w, q[4 * e4 + 3], a1);
        }
        r0[g] = a0; r1[g] = a1;
    }
    float t0 = st0[0], t1 = st0[1];
    #pragma unroll
    for (int e = 0; e < 32; e++) {
        t0 = fmaf(su[e], q[e], t0);
        t1 = fmaf(su[32 + e], q[e], t1);
    }

    // ---- K pass: stage each s-slab coalesced, compute logits ----
    const float4* ksrc = (const float4*)(key + (size_t)B0 * 288);
    float l0[SEQ], l1[SEQ];
    #pragma unroll
    for (int s = 0; s < SEQ; s++) {
        __syncwarp();   // prior consumption done before overwrite
        #pragma unroll
        for (int p = 0; p < 8; p++) {
            int f = p * 32 + lane;
            int row = f >> 3, c4 = f & 7;
            int r = row <= maxrow ? row : maxrow;
            float4 v = ksrc[r * 72 + s * 8 + c4];
            *(float4*)&buf[row * ROWSTRIDE + c4 * 4] = v;
        }
        __syncwarp();
        float d0 = t0, d1 = t1;
        #pragma unroll
        for (int e4 = 0; e4 < 8; e4++) {
            float4 kv = *(const float4*)&buf[lane * ROWSTRIDE + e4 * 4];
            d0 = fmaf(r0[4 * e4 + 0], kv.x, d0);
            d0 = fmaf(r0[4 * e4 + 1], kv.y, d0);
            d0 = fmaf(r0[4 * e4 + 2], kv.z, d0);
            d0 = fmaf(r0[4 * e4 + 3], kv.w, d0);
            d1 = fmaf(r1[4 * e4 + 0], kv.x, d1);
            d1 = fmaf(r1[4 * e4 + 1], kv.y, d1);
            d1 = fmaf(r1[4 * e4 + 2], kv.z, d1);
            d1 = fmaf(r1[4 * e4 + 3], kv.w, d1);
        }
        float gw = __expf(-10.0f * gb[lane * SEQ + s]);   // SIGMA = 10
        l0[s] = d0 * gw;
        l1[s] = d1 * gw;
    }

    // ---- softmax over S per head ----
    float m0 = l0[0], m1 = l1[0];
    #pragma unroll
    for (int s = 1; s < SEQ; s++) { m0 = fmaxf(m0, l0[s]); m1 = fmaxf(m1, l1[s]); }
    float p0[SEQ], p1[SEQ];
    float sum0 = 0.f, sum1 = 0.f;
    #pragma unroll
    for (int s = 0; s < SEQ; s++) {
        p0[s] = __expf(l0[s] - m0); sum0 += p0[s];
        p1[s] = __expf(l1[s] - m1); sum1 += p1[s];
    }
    float inv0 = __frcp_rn(sum0), inv1 = __frcp_rn(sum1);
    #pragma unroll
    for (int s = 0; s < SEQ; s++) { p0[s] *= inv0; p1[s] *= inv1; }

    // ---- V pass: stage each s-slab coalesced, accumulate weighted sums ----
    float vs0[32], vs1[32];
    #pragma unroll
    for (int g = 0; g < 32; g++) { vs0[g] = 0.f; vs1[g] = 0.f; }
    const float4* vsrc = (const float4*)(value + (size_t)B0 * 288);
    #pragma unroll
    for (int s = 0; s < SEQ; s++) {
        __syncwarp();
        #pragma unroll
        for (int p = 0; p < 8; p++) {
            int f = p * 32 + lane;
            int row = f >> 3, c4 = f & 7;
            int r = row <= maxrow ? row : maxrow;
            float4 v = vsrc[r * 72 + s * 8 + c4];
            *(float4*)&buf[row * ROWSTRIDE + c4 * 4] = v;
        }
        __syncwarp();
        float w0 = p0[s], w1 = p1[s];
        #pragma unroll
        for (int e4 = 0; e4 < 8; e4++) {
            float4 vv = *(const float4*)&buf[lane * ROWSTRIDE + e4 * 4];
            vs0[4 * e4 + 0] = fmaf(w0, vv.x, vs0[4 * e4 + 0]);
            vs0[4 * e4 + 1] = fmaf(w0, vv.y, vs0[4 * e4 + 1]);
            vs0[4 * e4 + 2] = fmaf(w0, vv.z, vs0[4 * e4 + 2]);
            vs0[4 * e4 + 3] = fmaf(w0, vv.w, vs0[4 * e4 + 3]);
            vs1[4 * e4 + 0] = fmaf(w1, vv.x, vs1[4 * e4 + 0]);
            vs1[4 * e4 + 1] = fmaf(w1, vv.y, vs1[4 * e4 + 1]);
            vs1[4 * e4 + 2] = fmaf(w1, vv.z, vs1[4 * e4 + 2]);
            vs1[4 * e4 + 3] = fmaf(w1, vv.w, vs1[4 * e4 + 3]);
        }
    }

    // ---- out[f] = M0[f]·vs0 + M1[f]·vs1 + D[f]; stage to smem, write coalesced ----
    const float4* M0 = (const float4*)sM;
    const float4* M1 = (const float4*)(sM + 1024);
    __syncwarp();
    #pragma unroll
    for (int f4 = 0; f4 < 8; f4++) {
        float ov[4];
        #pragma unroll
        for (int kk = 0; kk < 4; kk++) {
            int f = f4 * 4 + kk;
            float acc = sD[f];
            #pragma unroll
            for (int g4 = 0; g4 < 8; g4++) {
                float4 m0v = M0[f * 8 + g4];
                float4 m1v = M1[f * 8 + g4];
                acc = fmaf(m0v.x, vs0[4 * g4 + 0], acc);
                acc = fmaf(m0v.y, vs0[4 * g4 + 1], acc);
                acc = fmaf(m0v.z, vs0[4 * g4 + 2], acc);
                acc = fmaf(m0v.w, vs0[4 * g4 + 3], acc);
                acc = fmaf(m1v.x, vs1[4 * g4 + 0], acc);
                acc = fmaf(m1v.y, vs1[4 * g4 + 1], acc);
                acc = fmaf(m1v.z, vs1[4 * g4 + 2], acc);
                acc = fmaf(m1v.w, vs1[4 * g4 + 3], acc);
            }
            ov[kk] = acc;
        }
        *(float4*)&buf[lane * ROWSTRIDE + f4 * 4] = make_float4(ov[0], ov[1], ov[2], ov[3]);
    }
    __syncwarp();
    {
        float4* odst = (float4*)(out + (size_t)B0 * 32);
        #pragma unroll
        for (int p = 0; p < 8; p++) {
            int f = p * 32 + lane;
            int row = f >> 3, c4 = f & 7;
            if (row <= maxrow) {
                float4 v = *(const float4*)&buf[row * ROWSTRIDE + c4 * 4];
                odst[row * 8 + c4] = v;
            }
        }
    }
}

extern "C" void kernel_launch(void* const* d_in, const int* in_sizes, int n_in,
                              void* d_out, int out_size) {
    const float* query = (const float*)d_in[0];
    const float* key   = (const float*)d_in[1];
    const float* value = (const float*)d_in[2];
    const float* gauss = (const float*)d_in[3];
    const float* ipw   = (const float*)d_in[4];
    const float* ipb   = (const float*)d_in[5];
    const float* opw   = (const float*)d_in[6];
    const float* opb   = (const float*)d_in[7];
    float* out = (float*)d_out;

    int n = in_sizes[0] / 32;   // N batch elements (T=1, E=32)

    prep_kernel<<<1, 256>>>(ipw, ipb, opw, opb);
    attn_kernel<<<(n + 127) / 128, 128>>>(query, key, value, gauss, out, n);
}

// round 4
// speedup vs baseline: 1.3198x; 1.0937x over previous
#include <cuda_runtime.h>

// Fused gauss-attention, N=262144, T=1, S=9, E=32, H=2, HD=16.
// Round 4: octet decomposition — 8 threads per batch element, feature chunk
// of 4 floats per thread. All global accesses natively coalesced (LDG.128 /
// STG.128 full lines). Merged-weight math identical to rounds 1-3.

#define SEQ 9

// Merged weights in block layout blk[j][i][o][c] = Mat[4o+i][4j+c]
// (per head, 1024 floats each). Octet lane o reads float4 at
// j*128 + i*32 + o*4 -> banks cover 0..31 exactly once per (j,i).
__device__ float g_PB[2 * 1024];
__device__ float g_MB[2 * 1024];
__device__ float g_rb[2 * 32];
__device__ float g_u[2 * 32];
__device__ float g_t0[2];
__device__ float g_D[32];

__global__ void prep_kernel(const float* __restrict__ ipw,
                            const float* __restrict__ ipb,
                            const float* __restrict__ opw,
                            const float* __restrict__ opb) {
    const float* wq = ipw;
    const float* wk = ipw + 1024;
    const float* wv = ipw + 2048;
    const float* bq = ipb;
    const float* bk = ipb + 32;
    const float* bv = ipb + 64;
    int tid = threadIdx.x;

    for (int idx = tid; idx < 2048; idx += blockDim.x) {
        int h = idx >> 10;
        int a = (idx >> 5) & 31;   // row (P: g, M: f)
        int c = idx & 31;          // col (P: e, M: g)
        float accP = 0.f, accM = 0.f;
        #pragma unroll
        for (int d = 0; d < 16; d++) {
            int f = h * 16 + d;
            accP += wk[f * 32 + a] * wq[f * 32 + c];
            accM += opw[a * 32 + f] * wv[f * 32 + c];
        }
        int blk = h * 1024 + (c >> 2) * 128 + (a & 3) * 32 + (a >> 2) * 4 + (c & 3);
        g_PB[blk] = 0.25f * accP;
        g_MB[blk] = accM;
    }
    if (tid < 64) {
        int h = tid >> 5, j = tid & 31;
        float arb = 0.f, au = 0.f;
        #pragma unroll
        for (int d = 0; d < 16; d++) {
            int f = h * 16 + d;
            arb += bq[f] * wk[f * 32 + j];
            au  += wq[f * 32 + j] * bk[f];
        }
        g_rb[tid] = 0.25f * arb;
        g_u[tid]  = 0.25f * au;
    }
    if (tid < 32) {
        float acc = opb[tid];
        #pragma unroll
        for (int e = 0; e < 32; e++) acc += opw[tid * 32 + e] * bv[e];
        g_D[tid] = acc;
    }
    if (tid < 2) {
        float acc = 0.f;
        #pragma unroll
        for (int d = 0; d < 16; d++) acc += bq[tid * 16 + d] * bk[tid * 16 + d];
        g_t0[tid] = 0.25f * acc;
    }
}

__global__ void __launch_bounds__(128)
attn_kernel(const float* __restrict__ query, const float* __restrict__ key,
            const float* __restrict__ value, const float* __restrict__ gauss,
            float* __restrict__ out, int n) {
    __shared__ __align__(16) float sPB[2048];
    __shared__ __align__(16) float sMB[2048];
    __shared__ float srb[64];
    __shared__ float su[64];
    __shared__ float st0[2];
    __shared__ float sD[32];

    int tid = threadIdx.x;
    for (int i = tid; i < 2048; i += 128) {
        sPB[i] = g_PB[i];
        sMB[i] = g_MB[i];
    }
    if (tid < 64) { srb[tid] = g_rb[tid]; su[tid] = g_u[tid]; }
    if (tid < 32) sD[tid] = g_D[tid];
    if (tid < 2)  st0[tid] = g_t0[tid];
    __syncthreads();

    const int lane  = tid & 31;
    const int o     = lane & 7;        // feature-chunk owner within octet
    const int obase = lane & 24;       // first lane of this octet

    const float4* qptr = (const float4*)query;
    const float4* kptr = (const float4*)key;
    const float4* vptr = (const float4*)value;
    float4*       optr = (float4*)out;

    const int nquads = (n + 3) >> 2;                       // 4 batches per warp
    const int warp_g = (blockIdx.x * 128 + tid) >> 5;
    const int wstep  = (gridDim.x * 128) >> 5;

    for (int quad = warp_g; quad < nquads; quad += wstep) {
        int b = quad * 4 + (lane >> 3);
        bool valid = b < n;
        int bl = valid ? b : n - 1;

        // ---- load own q chunk (coalesced LDG.128) ----
        float4 q4 = qptr[(size_t)bl * 8 + o];

        // ---- r chunks (4 per head) + scalar t partials ----
        float r0[4], r1[4];
        #pragma unroll
        for (int gi = 0; gi < 4; gi++) {
            r0[gi] = srb[o * 4 + gi];
            r1[gi] = srb[32 + o * 4 + gi];
        }
        float tp0 = su[o * 4 + 0] * q4.x + su[o * 4 + 1] * q4.y
                  + su[o * 4 + 2] * q4.z + su[o * 4 + 3] * q4.w;
        float tp1 = su[32 + o * 4 + 0] * q4.x + su[32 + o * 4 + 1] * q4.y
                  + su[32 + o * 4 + 2] * q4.z + su[32 + o * 4 + 3] * q4.w;

        #pragma unroll
        for (int j = 0; j < 8; j++) {
            float qx = __shfl_sync(0xffffffffu, q4.x, obase + j);
            float qy = __shfl_sync(0xffffffffu, q4.y, obase + j);
            float qz = __shfl_sync(0xffffffffu, q4.z, obase + j);
            float qw = __shfl_sync(0xffffffffu, q4.w, obase + j);
            #pragma unroll
            for (int gi = 0; gi < 4; gi++) {
                float4 p0 = *(const float4*)&sPB[j * 128 + gi * 32 + o * 4];
                float4 p1 = *(const float4*)&sPB[1024 + j * 128 + gi * 32 + o * 4];
                r0[gi] = fmaf(p0.x, qx, r0[gi]);
                r0[gi] = fmaf(p0.y, qy, r0[gi]);
                r0[gi] = fmaf(p0.z, qz, r0[gi]);
                r0[gi] = fmaf(p0.w, qw, r0[gi]);
                r1[gi] = fmaf(p1.x, qx, r1[gi]);
                r1[gi] = fmaf(p1.y, qy, r1[gi]);
                r1[gi] = fmaf(p1.z, qz, r1[gi]);
                r1[gi] = fmaf(p1.w, qw, r1[gi]);
            }
        }
        // octet-reduce t partials
        tp0 += __shfl_xor_sync(0xffffffffu, tp0, 4);
        tp0 += __shfl_xor_sync(0xffffffffu, tp0, 2);
        tp0 += __shfl_xor_sync(0xffffffffu, tp0, 1);
        tp1 += __shfl_xor_sync(0xffffffffu, tp1, 4);
        tp1 += __shfl_xor_sync(0xffffffffu, tp1, 2);
        tp1 += __shfl_xor_sync(0xffffffffu, tp1, 1);
        tp0 += st0[0];
        tp1 += st0[1];

        // ---- logits over S keys ----
        float l0[SEQ], l1[SEQ];
        #pragma unroll
        for (int s = 0; s < SEQ; s++) {
            float4 kv = kptr[(size_t)bl * 72 + s * 8 + o];
            float d0 = r0[0] * kv.x;
            d0 = fmaf(r0[1], kv.y, d0);
            d0 = fmaf(r0[2], kv.z, d0);
            d0 = fmaf(r0[3], kv.w, d0);
            float d1 = r1[0] * kv.x;
            d1 = fmaf(r1[1], kv.y, d1);
            d1 = fmaf(r1[2], kv.z, d1);
            d1 = fmaf(r1[3], kv.w, d1);
            d0 += __shfl_xor_sync(0xffffffffu, d0, 4);
            d0 += __shfl_xor_sync(0xffffffffu, d0, 2);
            d0 += __shfl_xor_sync(0xffffffffu, d0, 1);
            d1 += __shfl_xor_sync(0xffffffffu, d1, 4);
            d1 += __shfl_xor_sync(0xffffffffu, d1, 2);
            d1 += __shfl_xor_sync(0xffffffffu, d1, 1);
            float gw = __expf(-10.0f * __ldg(&gauss[(size_t)bl * SEQ + s]));
            l0[s] = (d0 + tp0) * gw;
            l1[s] = (d1 + tp1) * gw;
        }

        // ---- softmax (redundant per octet lane, identical results) ----
        float m0 = l0[0], m1 = l1[0];
        #pragma unroll
        for (int s = 1; s < SEQ; s++) { m0 = fmaxf(m0, l0[s]); m1 = fmaxf(m1, l1[s]); }
        float sum0 = 0.f, sum1 = 0.f;
        #pragma unroll
        for (int s = 0; s < SEQ; s++) {
            l0[s] = __expf(l0[s] - m0); sum0 += l0[s];
            l1[s] = __expf(l1[s] - m1); sum1 += l1[s];
        }
        float inv0 = __frcp_rn(sum0), inv1 = __frcp_rn(sum1);
        #pragma unroll
        for (int s = 0; s < SEQ; s++) { l0[s] *= inv0; l1[s] *= inv1; }

        // ---- weighted V sums (own chunk, both heads) ----
        float4 a0 = make_float4(0.f, 0.f, 0.f, 0.f);
        float4 a1 = make_float4(0.f, 0.f, 0.f, 0.f);
        #pragma unroll
        for (int s = 0; s < SEQ; s++) {
            float4 vv = vptr[(size_t)bl * 72 + s * 8 + o];
            a0.x = fmaf(l0[s], vv.x, a0.x);
            a0.y = fmaf(l0[s], vv.y, a0.y);
            a0.z = fmaf(l0[s], vv.z, a0.z);
            a0.w = fmaf(l0[s], vv.w, a0.w);
            a1.x = fmaf(l1[s], vv.x, a1.x);
            a1.y = fmaf(l1[s], vv.y, a1.y);
            a1.z = fmaf(l1[s], vv.z, a1.z);
            a1.w = fmaf(l1[s], vv.w, a1.w);
        }

        // ---- out chunk: out[4o+fi] = D + M0[f]·vs0 + M1[f]·vs1 ----
        float ov[4];
        #pragma unroll
        for (int fi = 0; fi < 4; fi++) ov[fi] = sD[o * 4 + fi];
        #pragma unroll
        for (int j = 0; j < 8; j++) {
            float v0x = __shfl_sync(0xffffffffu, a0.x, obase + j);
            float v0y = __shfl_sync(0xffffffffu, a0.y, obase + j);
            float v0z = __shfl_sync(0xffffffffu, a0.z, obase + j);
            float v0w = __shfl_sync(0xffffffffu, a0.w, obase + j);
            float v1x = __shfl_sync(0xffffffffu, a1.x, obase + j);
            float v1y = __shfl_sync(0xffffffffu, a1.y, obase + j);
            float v1z = __shfl_sync(0xffffffffu, a1.z, obase + j);
            float v1w = __shfl_sync(0xffffffffu, a1.w, obase + j);
            #pragma unroll
            for (int fi = 0; fi < 4; fi++) {
                float4 m0 = *(const float4*)&sMB[j * 128 + fi * 32 + o * 4];
                float4 m1 = *(const float4*)&sMB[1024 + j * 128 + fi * 32 + o * 4];
                ov[fi] = fmaf(m0.x, v0x, ov[fi]);
                ov[fi] = fmaf(m0.y, v0y, ov[fi]);
                ov[fi] = fmaf(m0.z, v0z, ov[fi]);
                ov[fi] = fmaf(m0.w, v0w, ov[fi]);
                ov[fi] = fmaf(m1.x, v1x, ov[fi]);
                ov[fi] = fmaf(m1.y, v1y, ov[fi]);
                ov[fi] = fmaf(m1.z, v1z, ov[fi]);
                ov[fi] = fmaf(m1.w, v1w, ov[fi]);
            }
        }
        if (valid) {
            optr[(size_t)b * 8 + o] = make_float4(ov[0], ov[1], ov[2], ov[3]);
        }
    }
}

extern "C" void kernel_launch(void* const* d_in, const int* in_sizes, int n_in,
                              void* d_out, int out_size) {
    const float* query = (const float*)d_in[0];
    const float* key   = (const float*)d_in[1];
    const float* value = (const float*)d_in[2];
    const float* gauss = (const float*)d_in[3];
    const float* ipw   = (const float*)d_in[4];
    const float* ipb   = (const float*)d_in[5];
    const float* opw   = (const float*)d_in[6];
    const float* opb   = (const float*)d_in[7];
    float* out = (float*)d_out;

    int n = in_sizes[0] / 32;   // N batch elements (T=1, E=32)

    prep_kernel<<<1, 256>>>(ipw, ipb, opw, opb);
    attn_kernel<<<1184, 128>>>(query, key, value, gauss, out, n);
}

// round 5
// speedup vs baseline: 1.3821x; 1.0471x over previous
#include <cuda_runtime.h>

// Fused gauss-attention, N=262144, T=1, S=9, E=32, H=2, HD=16.
// Round 5: octet decomposition + 2-quad blocking. Each warp iteration handles
// 8 batches; the smem weight reads in the P (r = P q) and M (out = M vs)
// matvecs are loaded ONCE per iteration and applied to both quads, halving
// per-batch shared-memory traffic (round-4 profile: L1/shared pipe 82% was
// the binding resource).

#define SEQ 9

// Merged weights in block layout blk[j][i][o][c] = Mat[4o+i][4j+c]
// (per head, 1024 floats each).
__device__ float g_PB[2 * 1024];
__device__ float g_MB[2 * 1024];
__device__ float g_rb[2 * 32];
__device__ float g_u[2 * 32];
__device__ float g_t0[2];
__device__ float g_D[32];

__global__ void prep_kernel(const float* __restrict__ ipw,
                            const float* __restrict__ ipb,
                            const float* __restrict__ opw,
                            const float* __restrict__ opb) {
    const float* wq = ipw;
    const float* wk = ipw + 1024;
    const float* wv = ipw + 2048;
    const float* bq = ipb;
    const float* bk = ipb + 32;
    const float* bv = ipb + 64;
    int tid = threadIdx.x;

    for (int idx = tid; idx < 2048; idx += blockDim.x) {
        int h = idx >> 10;
        int a = (idx >> 5) & 31;   // row (P: g, M: f)
        int c = idx & 31;          // col (P: e, M: g)
        float accP = 0.f, accM = 0.f;
        #pragma unroll
        for (int d = 0; d < 16; d++) {
            int f = h * 16 + d;
            accP += wk[f * 32 + a] * wq[f * 32 + c];
            accM += opw[a * 32 + f] * wv[f * 32 + c];
        }
        int blk = h * 1024 + (c >> 2) * 128 + (a & 3) * 32 + (a >> 2) * 4 + (c & 3);
        g_PB[blk] = 0.25f * accP;
        g_MB[blk] = accM;
    }
    if (tid < 64) {
        int h = tid >> 5, j = tid & 31;
        float arb = 0.f, au = 0.f;
        #pragma unroll
        for (int d = 0; d < 16; d++) {
            int f = h * 16 + d;
            arb += bq[f] * wk[f * 32 + j];
            au  += wq[f * 32 + j] * bk[f];
        }
        g_rb[tid] = 0.25f * arb;
        g_u[tid]  = 0.25f * au;
    }
    if (tid < 32) {
        float acc = opb[tid];
        #pragma unroll
        for (int e = 0; e < 32; e++) acc += opw[tid * 32 + e] * bv[e];
        g_D[tid] = acc;
    }
    if (tid < 2) {
        float acc = 0.f;
        #pragma unroll
        for (int d = 0; d < 16; d++) acc += bq[tid * 16 + d] * bk[tid * 16 + d];
        g_t0[tid] = 0.25f * acc;
    }
}

__global__ void __launch_bounds__(128)
attn_kernel(const float* __restrict__ query, const float* __restrict__ key,
            const float* __restrict__ value, const float* __restrict__ gauss,
            float* __restrict__ out, int n) {
    __shared__ __align__(16) float sPB[2048];
    __shared__ __align__(16) float sMB[2048];
    __shared__ float srb[64];
    __shared__ float su[64];
    __shared__ float st0[2];
    __shared__ float sD[32];

    int tid = threadIdx.x;
    for (int i = tid; i < 2048; i += 128) {
        sPB[i] = g_PB[i];
        sMB[i] = g_MB[i];
    }
    if (tid < 64) { srb[tid] = g_rb[tid]; su[tid] = g_u[tid]; }
    if (tid < 32) sD[tid] = g_D[tid];
    if (tid < 2)  st0[tid] = g_t0[tid];
    __syncthreads();

    const int lane  = tid & 31;
    const int o     = lane & 7;        // feature-chunk owner within octet
    const int obase = lane & 24;       // first lane of this octet
    const int trow  = lane >> 3;       // which batch of the quad

    const float4* qptr = (const float4*)query;
    const float4* kptr = (const float4*)key;
    const float4* vptr = (const float4*)value;
    float4*       optr = (float4*)out;

    // each warp iteration handles 8 batches (2 quads)
    const int ngroups = (n + 7) >> 3;
    const int warp_g  = (blockIdx.x * 128 + tid) >> 5;
    const int wstep   = (gridDim.x * 128) >> 5;

    for (int grp = warp_g; grp < ngroups; grp += wstep) {
        int bA = grp * 8 + trow;
        int bB = bA + 4;
        int blA = bA < n ? bA : n - 1;
        int blB = bB < n ? bB : n - 1;

        // ---- load own q chunks (coalesced LDG.128) ----
        float4 qA = qptr[(size_t)blA * 8 + o];
        float4 qB = qptr[(size_t)blB * 8 + o];

        // ---- r chunks (4 per head per quad) ----
        float rA0[4], rA1[4], rB0[4], rB1[4];
        #pragma unroll
        for (int gi = 0; gi < 4; gi++) {
            float b0 = srb[o * 4 + gi];
            float b1 = srb[32 + o * 4 + gi];
            rA0[gi] = b0; rB0[gi] = b0;
            rA1[gi] = b1; rB1[gi] = b1;
        }
        // scalar t partials
        float tA0 = su[o * 4 + 0] * qA.x + su[o * 4 + 1] * qA.y
                  + su[o * 4 + 2] * qA.z + su[o * 4 + 3] * qA.w;
        float tA1 = su[32 + o * 4 + 0] * qA.x + su[32 + o * 4 + 1] * qA.y
                  + su[32 + o * 4 + 2] * qA.z + su[32 + o * 4 + 3] * qA.w;
        float tB0 = su[o * 4 + 0] * qB.x + su[o * 4 + 1] * qB.y
                  + su[o * 4 + 2] * qB.z + su[o * 4 + 3] * qB.w;
        float tB1 = su[32 + o * 4 + 0] * qB.x + su[32 + o * 4 + 1] * qB.y
                  + su[32 + o * 4 + 2] * qB.z + su[32 + o * 4 + 3] * qB.w;

        // ---- P matvec: weights loaded once, applied to both quads ----
        #pragma unroll
        for (int j = 0; j < 8; j++) {
            float qAx = __shfl_sync(0xffffffffu, qA.x, obase + j);
            float qAy = __shfl_sync(0xffffffffu, qA.y, obase + j);
            float qAz = __shfl_sync(0xffffffffu, qA.z, obase + j);
            float qAw = __shfl_sync(0xffffffffu, qA.w, obase + j);
            float qBx = __shfl_sync(0xffffffffu, qB.x, obase + j);
            float qBy = __shfl_sync(0xffffffffu, qB.y, obase + j);
            float qBz = __shfl_sync(0xffffffffu, qB.z, obase + j);
            float qBw = __shfl_sync(0xffffffffu, qB.w, obase + j);
            #pragma unroll
            for (int gi = 0; gi < 4; gi++) {
                float4 p0 = *(const float4*)&sPB[j * 128 + gi * 32 + o * 4];
                float4 p1 = *(const float4*)&sPB[1024 + j * 128 + gi * 32 + o * 4];
                rA0[gi] = fmaf(p0.x, qAx, rA0[gi]);
                rA0[gi] = fmaf(p0.y, qAy, rA0[gi]);
                rA0[gi] = fmaf(p0.z, qAz, rA0[gi]);
                rA0[gi] = fmaf(p0.w, qAw, rA0[gi]);
                rB0[gi] = fmaf(p0.x, qBx, rB0[gi]);
                rB0[gi] = fmaf(p0.y, qBy, rB0[gi]);
                rB0[gi] = fmaf(p0.z, qBz, rB0[gi]);
                rB0[gi] = fmaf(p0.w, qBw, rB0[gi]);
                rA1[gi] = fmaf(p1.x, qAx, rA1[gi]);
                rA1[gi] = fmaf(p1.y, qAy, rA1[gi]);
                rA1[gi] = fmaf(p1.z, qAz, rA1[gi]);
                rA1[gi] = fmaf(p1.w, qAw, rA1[gi]);
                rB1[gi] = fmaf(p1.x, qBx, rB1[gi]);
                rB1[gi] = fmaf(p1.y, qBy, rB1[gi]);
                rB1[gi] = fmaf(p1.z, qBz, rB1[gi]);
                rB1[gi] = fmaf(p1.w, qBw, rB1[gi]);
            }
        }
        // octet-reduce t partials
        #pragma unroll
        for (int d = 4; d >= 1; d >>= 1) {
            tA0 += __shfl_xor_sync(0xffffffffu, tA0, d);
            tA1 += __shfl_xor_sync(0xffffffffu, tA1, d);
            tB0 += __shfl_xor_sync(0xffffffffu, tB0, d);
            tB1 += __shfl_xor_sync(0xffffffffu, tB1, d);
        }
        tA0 += st0[0]; tA1 += st0[1];
        tB0 += st0[0]; tB1 += st0[1];

        // ---- per-quad: K stream -> logits -> softmax -> V stream ----
        float4 aA0, aA1, aB0, aB1;
        #pragma unroll
        for (int half = 0; half < 2; half++) {
            int bl = half ? blB : blA;
            float r0x = half ? rB0[0] : rA0[0];
            float r0y = half ? rB0[1] : rA0[1];
            float r0z = half ? rB0[2] : rA0[2];
            float r0w = half ? rB0[3] : rA0[3];
            float r1x = half ? rB1[0] : rA1[0];
            float r1y = half ? rB1[1] : rA1[1];
            float r1z = half ? rB1[2] : rA1[2];
            float r1w = half ? rB1[3] : rA1[3];
            float t0 = half ? tB0 : tA0;
            float t1 = half ? tB1 : tA1;

            float l0[SEQ], l1[SEQ];
            #pragma unroll
            for (int s = 0; s < SEQ; s++) {
                float4 kv = kptr[(size_t)bl * 72 + s * 8 + o];
                float d0 = r0x * kv.x;
                d0 = fmaf(r0y, kv.y, d0);
                d0 = fmaf(r0z, kv.z, d0);
                d0 = fmaf(r0w, kv.w, d0);
                float d1 = r1x * kv.x;
                d1 = fmaf(r1y, kv.y, d1);
                d1 = fmaf(r1z, kv.z, d1);
                d1 = fmaf(r1w, kv.w, d1);
                d0 += __shfl_xor_sync(0xffffffffu, d0, 4);
                d0 += __shfl_xor_sync(0xffffffffu, d0, 2);
                d0 += __shfl_xor_sync(0xffffffffu, d0, 1);
                d1 += __shfl_xor_sync(0xffffffffu, d1, 4);
                d1 += __shfl_xor_sync(0xffffffffu, d1, 2);
                d1 += __shfl_xor_sync(0xffffffffu, d1, 1);
                float gw = __expf(-10.0f * __ldg(&gauss[(size_t)bl * SEQ + s]));
                l0[s] = (d0 + t0) * gw;
                l1[s] = (d1 + t1) * gw;
            }

            float m0 = l0[0], m1 = l1[0];
            #pragma unroll
            for (int s = 1; s < SEQ; s++) { m0 = fmaxf(m0, l0[s]); m1 = fmaxf(m1, l1[s]); }
            float sum0 = 0.f, sum1 = 0.f;
            #pragma unroll
            for (int s = 0; s < SEQ; s++) {
                l0[s] = __expf(l0[s] - m0); sum0 += l0[s];
                l1[s] = __expf(l1[s] - m1); sum1 += l1[s];
            }
            float inv0 = __frcp_rn(sum0), inv1 = __frcp_rn(sum1);

            float4 a0 = make_float4(0.f, 0.f, 0.f, 0.f);
            float4 a1 = make_float4(0.f, 0.f, 0.f, 0.f);
            #pragma unroll
            for (int s = 0; s < SEQ; s++) {
                float4 vv = vptr[(size_t)bl * 72 + s * 8 + o];
                a0.x = fmaf(l0[s], vv.x, a0.x);
                a0.y = fmaf(l0[s], vv.y, a0.y);
                a0.z = fmaf(l0[s], vv.z, a0.z);
                a0.w = fmaf(l0[s], vv.w, a0.w);
                a1.x = fmaf(l1[s], vv.x, a1.x);
                a1.y = fmaf(l1[s], vv.y, a1.y);
                a1.z = fmaf(l1[s], vv.z, a1.z);
                a1.w = fmaf(l1[s], vv.w, a1.w);
            }
            a0.x *= inv0; a0.y *= inv0; a0.z *= inv0; a0.w *= inv0;
            a1.x *= inv1; a1.y *= inv1; a1.z *= inv1; a1.w *= inv1;
            if (half) { aB0 = a0; aB1 = a1; } else { aA0 = a0; aA1 = a1; }
        }

        // ---- M matvec: weights loaded once, applied to both quads ----
        float ovA[4], ovB[4];
        #pragma unroll
        for (int fi = 0; fi < 4; fi++) {
            float dd = sD[o * 4 + fi];
            ovA[fi] = dd; ovB[fi] = dd;
        }
        #pragma unroll
        for (int j = 0; j < 8; j++) {
            float vA0x = __shfl_sync(0xffffffffu, aA0.x, obase + j);
            float vA0y = __shfl_sync(0xffffffffu, aA0.y, obase + j);
            float vA0z = __shfl_sync(0xffffffffu, aA0.z, obase + j);
            float vA0w = __shfl_sync(0xffffffffu, aA0.w, obase + j);
            float vA1x = __shfl_sync(0xffffffffu, aA1.x, obase + j);
            float vA1y = __shfl_sync(0xffffffffu, aA1.y, obase + j);
            float vA1z = __shfl_sync(0xffffffffu, aA1.z, obase + j);
            float vA1w = __shfl_sync(0xffffffffu, aA1.w, obase + j);
            float vB0x = __shfl_sync(0xffffffffu, aB0.x, obase + j);
            float vB0y = __shfl_sync(0xffffffffu, aB0.y, obase + j);
            float vB0z = __shfl_sync(0xffffffffu, aB0.z, obase + j);
            float vB0w = __shfl_sync(0xffffffffu, aB0.w, obase + j);
            float vB1x = __shfl_sync(0xffffffffu, aB1.x, obase + j);
            float vB1y = __shfl_sync(0xffffffffu, aB1.y, obase + j);
            float vB1z = __shfl_sync(0xffffffffu, aB1.z, obase + j);
            float vB1w = __shfl_sync(0xffffffffu, aB1.w, obase + j);
            #pragma unroll
            for (int fi = 0; fi < 4; fi++) {
                float4 m0 = *(const float4*)&sMB[j * 128 + fi * 32 + o * 4];
                float4 m1 = *(const float4*)&sMB[1024 + j * 128 + fi * 32 + o * 4];
                ovA[fi] = fmaf(m0.x, vA0x, ovA[fi]);
                ovA[fi] = fmaf(m0.y, vA0y, ovA[fi]);
                ovA[fi] = fmaf(m0.z, vA0z, ovA[fi]);
                ovA[fi] = fmaf(m0.w, vA0w, ovA[fi]);
                ovA[fi] = fmaf(m1.x, vA1x, ovA[fi]);
                ovA[fi] = fmaf(m1.y, vA1y, ovA[fi]);
                ovA[fi] = fmaf(m1.z, vA1z, ovA[fi]);
                ovA[fi] = fmaf(m1.w, vA1w, ovA[fi]);
                ovB[fi] = fmaf(m0.x, vB0x, ovB[fi]);
                ovB[fi] = fmaf(m0.y, vB0y, ovB[fi]);
                ovB[fi] = fmaf(m0.z, vB0z, ovB[fi]);
                ovB[fi] = fmaf(m0.w, vB0w, ovB[fi]);
                ovB[fi] = fmaf(m1.x, vB1x, ovB[fi]);
                ovB[fi] = fmaf(m1.y, vB1y, ovB[fi]);
                ovB[fi] = fmaf(m1.z, vB1z, ovB[fi]);
                ovB[fi] = fmaf(m1.w, vB1w, ovB[fi]);
            }
        }
        if (bA < n) optr[(size_t)bA * 8 + o] = make_float4(ovA[0], ovA[1], ovA[2], ovA[3]);
        if (bB < n) optr[(size_t)bB * 8 + o] = make_float4(ovB[0], ovB[1], ovB[2], ovB[3]);
    }
}

extern "C" void kernel_launch(void* const* d_in, const int* in_sizes, int n_in,
                              void* d_out, int out_size) {
    const float* query = (const float*)d_in[0];
    const float* key   = (const float*)d_in[1];
    const float* value = (const float*)d_in[2];
    const float* gauss = (const float*)d_in[3];
    const float* ipw   = (const float*)d_in[4];
    const float* ipb   = (const float*)d_in[5];
    const float* opw   = (const float*)d_in[6];
    const float* opb   = (const float*)d_in[7];
    float* out = (float*)d_out;

    int n = in_sizes[0] / 32;   // N batch elements (T=1, E=32)

    prep_kernel<<<1, 256>>>(ipw, ipb, opw, opb);
    attn_kernel<<<1184, 128>>>(query, key, value, gauss, out, n);
}